// round 9
// baseline (speedup 1.0000x reference)
#include <cuda_runtime.h>
#include <cuda_bf16.h>
#include <cstdint>

// ---------------- problem constants ----------------
#define C_CLS   201
#define K_PROT  5
#define DIM     768
#define B_IMG   64
#define NP      256
#define BN_TOT  16384
#define CK      1005
#define NPAD    1024
#define KSPLIT  1536          // stored [hi | lo]; logical K = 2304 via chunk remap
#define EPSV    1e-12f

#define SZ_PP   (BN_TOT*CK)
#define SZ_IMG  (B_IMG*CK)
#define SZ_CLS  (B_IMG*(C_CLS-1))
#define SZ_PART (BN_TOT)
#define SZ_NP   (C_CLS*K_PROT*DIM)

// ---------------- device scratch ----------------
__device__ __nv_bfloat16 g_Abf[(size_t)BN_TOT*KSPLIT];   // 50.3 MB
__device__ __nv_bfloat16 g_Bbf[(size_t)NPAD*KSPLIT];     // 3.1 MB
__device__ float g_invA[BN_TOT];
__device__ int   g_rowlist[C_CLS*BN_TOT];
__device__ int   g_count[C_CLS];
__device__ float g_Q[BN_TOT*K_PROT];
__device__ float g_Pacc[SZ_NP];
__device__ float g_part[128*1024];    // per row-block column sums
__device__ int   g_wl[1024];          // packed (class<<16)|chunk
__device__ int   g_nw;

__device__ __forceinline__ uint32_t smem_u32(const void* p) {
    uint32_t a;
    asm("{ .reg .u64 t; cvta.to.shared.u64 t, %1; cvt.u32.u64 %0, t; }" : "=r"(a) : "l"(p));
    return a;
}

// ---------------- kernel 0: zero scratch ----------------
__global__ void zero_k() {
    int i = blockIdx.x * 256 + threadIdx.x;
    if (i < SZ_NP)  g_Pacc[i] = 0.0f;
    if (i < C_CLS)  g_count[i] = 0;
}

// ---------------- conv: normalize + bf16 hi/lo split, stored [hi|lo] ----------------
template <int MODE>   // 0: tokens -> g_Abf (+g_invA); 1: protos -> g_Bbf
__global__ void __launch_bounds__(256) conv_k(const float* __restrict__ in, int nrows) {
    int row = blockIdx.x;
    int tid = threadIdx.x;
    __shared__ float red[8];
    __nv_bfloat16* dst = (MODE == 0 ? g_Abf : g_Bbf) + (size_t)row * KSPLIT;

    if (MODE == 1 && row >= nrows) {
        __nv_bfloat16 z = __float2bfloat16(0.0f);
        for (int i = tid; i < KSPLIT; i += 256) dst[i] = z;
        return;
    }
    const float* rp = in + (size_t)row * DIM;
    float v[3]; float s = 0.0f;
#pragma unroll
    for (int i = 0; i < 3; i++) { v[i] = rp[tid + i*256]; s += v[i]*v[i]; }
#pragma unroll
    for (int o = 16; o; o >>= 1) s += __shfl_xor_sync(0xffffffffu, s, o);
    if ((tid & 31) == 0) red[tid >> 5] = s;
    __syncthreads();
    float tot = 0.0f;
#pragma unroll
    for (int w = 0; w < 8; w++) tot += red[w];
    float inv = 1.0f / (sqrtf(tot) + EPSV);
    if (MODE == 0 && tid == 0) g_invA[row] = inv;
#pragma unroll
    for (int i = 0; i < 3; i++) {
        float a = v[i] * inv;
        __nv_bfloat16 hi = __float2bfloat16(a);
        __nv_bfloat16 lo = __float2bfloat16(a - __bfloat162float(hi));
        int c = tid + i*256;
        dst[c] = hi; dst[768 + c] = lo;
    }
}

// ---------------- GEMM: mma.sync bf16, CTA 128x128, logical K=2304 ----------------
// logical chunks s=0..71: A' = [Ah|Ah|Al], B' = [Bh|Bl|Bh]
// physical: A chunk = s<24 ? s : s-24 ; B chunk = s<48 ? s : s-48
#define NSTAGE  72
#define STAGES  5
#define STG_BYTES 20480

__device__ __forceinline__ void ldsm4(uint32_t& r0, uint32_t& r1, uint32_t& r2, uint32_t& r3,
                                      uint32_t addr) {
    asm volatile("ldmatrix.sync.aligned.m8n8.x4.shared.b16 {%0,%1,%2,%3}, [%4];"
                 : "=r"(r0), "=r"(r1), "=r"(r2), "=r"(r3) : "r"(addr));
}
__device__ __forceinline__ void mma16816(float* c, const uint32_t* a, const uint32_t* b) {
    asm volatile("mma.sync.aligned.m16n8k16.row.col.f32.bf16.bf16.f32 "
                 "{%0,%1,%2,%3}, {%4,%5,%6,%7}, {%8,%9}, {%0,%1,%2,%3};"
                 : "+f"(c[0]), "+f"(c[1]), "+f"(c[2]), "+f"(c[3])
                 : "r"(a[0]), "r"(a[1]), "r"(a[2]), "r"(a[3]), "r"(b[0]), "r"(b[1]));
}
__device__ __forceinline__ void cpa16(uint32_t dst, const void* src) {
    asm volatile("cp.async.cg.shared.global [%0], [%1], 16;" :: "r"(dst), "l"(src));
}

__global__ void __launch_bounds__(128, 2) gemm_mma(float* __restrict__ Cout) {
    extern __shared__ char sm[];

    int tid = threadIdx.x;
    int lane = tid & 31;
    int warp = tid >> 5;
    int wm = warp & 1;            // m offset 64*wm
    int wn = warp >> 1;           // n offset 64*wn
    int row0 = blockIdx.y * 128;
    int col0 = blockIdx.x * 128;

    uint32_t sbase = smem_u32(sm);
    const char* gA = (const char*)g_Abf + (size_t)(row0 + tid) * (KSPLIT*2);
    const char* gB = (const char*)g_Bbf + (size_t)(col0 + tid) * (KSPLIT*2);

    uint32_t a_lane = (uint32_t)((((lane >> 3) & 1)*8 + (lane & 7))*80 + ((lane >> 4) & 1)*16);
    uint32_t b_lane = (uint32_t)((((lane >> 4) & 1)*8 + (lane & 7))*80 + ((lane >> 3) & 1)*16);
    uint32_t a_off = (uint32_t)(wm*64)*80 + a_lane;
    uint32_t b_off = 10240u + (uint32_t)(wn*64)*80 + b_lane;

    float acc[4][8][4];
#pragma unroll
    for (int i = 0; i < 4; i++)
#pragma unroll
        for (int j = 0; j < 8; j++)
#pragma unroll
            for (int r = 0; r < 4; r++) acc[i][j][r] = 0.0f;

    // prologue: issue stages 0..3 (identity chunk map for p<24)
#pragma unroll
    for (int p = 0; p < STAGES - 1; p++) {
        uint32_t dA = sbase + p*STG_BYTES + tid*80;
        const char* pA = gA + p*64;
        const char* pB = gB + p*64;
#pragma unroll
        for (int c = 0; c < 4; c++) {
            cpa16(dA + c*16, pA + c*16);
            cpa16(dA + 10240 + c*16, pB + c*16);
        }
        asm volatile("cp.async.commit_group;" ::: "memory");
    }

    int buf = 0;
    for (int s = 0; s < NSTAGE; s++) {
        asm volatile("cp.async.wait_group %0;" :: "n"(STAGES - 2) : "memory");
        __syncthreads();

        // issue prefetch for stage s+STAGES-1 FIRST (overlaps with mma below)
        if (s + STAGES - 1 < NSTAGE) {
            int p = s + STAGES - 1;
            int pa = (p < 24) ? p : (p - 24);     // A: [Ah|Ah|Al] -> [hi|lo]
            int pb = (p < 48) ? p : (p - 48);     // B: [Bh|Bl|Bh] -> [hi|lo]
            int pbuf = buf + STAGES - 1; if (pbuf >= STAGES) pbuf -= STAGES;
            uint32_t dA = sbase + (uint32_t)pbuf*STG_BYTES + tid*80;
            const char* pA = gA + pa*64;
            const char* pB = gB + pb*64;
#pragma unroll
            for (int c = 0; c < 4; c++) {
                cpa16(dA + c*16, pA + c*16);
                cpa16(dA + 10240 + c*16, pB + c*16);
            }
        }
        asm volatile("cp.async.commit_group;" ::: "memory");

        uint32_t stg = sbase + (uint32_t)buf*STG_BYTES;
        uint32_t ab = stg + a_off;
        uint32_t bb = stg + b_off;

        // preload ALL fragments for both ks halves, then run all mma
        uint32_t af[2][4][4], bf[2][4][4];
#pragma unroll
        for (int ks = 0; ks < 2; ks++) {
#pragma unroll
            for (int i = 0; i < 4; i++)
                ldsm4(af[ks][i][0], af[ks][i][1], af[ks][i][2], af[ks][i][3],
                      ab + ks*32 + i*16*80);
#pragma unroll
            for (int j = 0; j < 4; j++)
                ldsm4(bf[ks][j][0], bf[ks][j][1], bf[ks][j][2], bf[ks][j][3],
                      bb + ks*32 + j*16*80);
        }
#pragma unroll
        for (int ks = 0; ks < 2; ks++)
#pragma unroll
            for (int im = 0; im < 4; im++)
#pragma unroll
                for (int j = 0; j < 4; j++) {
                    mma16816(acc[im][2*j],   af[ks][im], &bf[ks][j][0]);
                    mma16816(acc[im][2*j+1], af[ks][im], &bf[ks][j][2]);
                }

        if (++buf == STAGES) buf = 0;
    }

    // ----- fused patch-mean partials: column sums over this CTA's 128 rows -----
    float cs[16];
#pragma unroll
    for (int j = 0; j < 8; j++)
#pragma unroll
        for (int h = 0; h < 2; h++) {
            float v = 0.0f;
#pragma unroll
            for (int im = 0; im < 4; im++) v += acc[im][j][h] + acc[im][j][h+2];
            cs[j*2+h] = v;
        }
#pragma unroll
    for (int o = 4; o <= 16; o <<= 1)
#pragma unroll
        for (int t = 0; t < 16; t++) cs[t] += __shfl_xor_sync(0xffffffffu, cs[t], o);

    __syncthreads();   // all MMA + cp.async done; reuse smem
    float* scol = (float*)sm;          // [2][128]
    if (lane < 4) {
#pragma unroll
        for (int j = 0; j < 8; j++) {
            scol[wm*128 + wn*64 + lane*2 + j*8]     = cs[j*2];
            scol[wm*128 + wn*64 + lane*2 + j*8 + 1] = cs[j*2+1];
        }
    }
    __syncthreads();
    if (tid < 128)
        g_part[blockIdx.y*1024 + col0 + tid] = scol[tid] + scol[128 + tid];

    // epilogue: scalar stores (CK=1005 odd -> rows not 8B aligned)
    int mb = row0 + wm*64 + (lane >> 2);
    int nb0 = col0 + wn*64 + (lane & 3)*2;
#pragma unroll
    for (int im = 0; im < 4; im++) {
        size_t r0 = (size_t)(mb + im*16) * CK;
        size_t r1 = (size_t)(mb + im*16 + 8) * CK;
#pragma unroll
        for (int j = 0; j < 8; j++) {
            int n = nb0 + j*8;
            if (n < CK) {
                Cout[r0 + n] = acc[im][j][0];
                Cout[r1 + n] = acc[im][j][2];
            }
            if (n + 1 < CK) {
                Cout[r0 + n + 1] = acc[im][j][1];
                Cout[r1 + n + 1] = acc[im][j][3];
            }
        }
    }
}

// ---------------- combine partial sums -> image logits ----------------
__global__ void mean2(float* __restrict__ img) {
    int idx = blockIdx.x * 256 + threadIdx.x;
    if (idx >= SZ_IMG) return;
    int b = idx / CK, ck = idx % CK;
    img[idx] = (g_part[(2*b)*1024 + ck] + g_part[(2*b+1)*1024 + ck]) * (1.0f/256.0f);
}

// ---------------- class logits ----------------
__global__ void cls_logits(const float* __restrict__ img, const float* __restrict__ sa,
                           const float* __restrict__ scale_p, float* __restrict__ out) {
    int idx = blockIdx.x * 256 + threadIdx.x;
    if (idx >= SZ_CLS) return;
    int b = idx / (C_CLS-1), c = idx % (C_CLS-1);
    float s[K_PROT], mx = -1e30f;
#pragma unroll
    for (int k = 0; k < K_PROT; k++) { s[k] = sa[c*K_PROT + k]; mx = fmaxf(mx, s[k]); }
    float den = 0.0f;
#pragma unroll
    for (int k = 0; k < K_PROT; k++) { s[k] = expf(s[k] - mx); den += s[k]; }
    float scale = scale_p[0];
    float acc = 0.0f;
#pragma unroll
    for (int k = 0; k < K_PROT; k++)
        acc += scale * img[b*CK + c*K_PROT + k] * (s[k] / den * (float)K_PROT);
    out[idx] = acc;
}

// ---------------- pseudo labels + per-class row lists ----------------
__global__ void pseudo_k(const int* __restrict__ labels, const unsigned* __restrict__ masks,
                         float* __restrict__ out_pl) {
    int bn = blockIdx.x * 256 + threadIdx.x;
    int b = bn >> 8;
    int lab = labels[b];
    int pl = (masks[bn] != 0u) ? lab : (C_CLS - 1);
    out_pl[bn] = (float)pl;
    int pos = atomicAdd(&g_count[pl], 1);
    g_rowlist[pl*BN_TOT + pos] = bn;
}

// ---------------- worklist: compact (class, chunk) pairs ----------------
#define PR 32
__global__ void worklist_k() {
    __shared__ int sc[256];
    int tid = threadIdx.x;
    int n = (tid < C_CLS) ? (g_count[tid] + PR - 1) / PR : 0;
    sc[tid] = n;
    __syncthreads();
    for (int off = 1; off < 256; off <<= 1) {
        int v = (tid >= off) ? sc[tid - off] : 0;
        __syncthreads();
        sc[tid] += v;
        __syncthreads();
    }
    int end = sc[tid];
    int start = end - n;
    for (int i = 0; i < n; i++) g_wl[start + i] = (tid << 16) | i;
    if (tid == 255) g_nw = sc[255];
}

// ---------------- per-class masked Sinkhorn + argmax ----------------
__global__ void __launch_bounds__(1024) sinkhorn_k(const float* __restrict__ L,
                                                   float* __restrict__ out_part) {
    int c = blockIdx.x;
    int M = g_count[c];
    if (M == 0) return;
    int tid = threadIdx.x;
    int lane = tid & 31;
    __shared__ float s_col[K_PROT];
    const int* rl = g_rowlist + c*BN_TOT;

    float ps[K_PROT];
#pragma unroll
    for (int k = 0; k < K_PROT; k++) ps[k] = 0.0f;

    for (int r = tid; r < M; r += 1024) {
        int n = rl[r];
        const float* lp = L + (size_t)n*CK + c*K_PROT;
        float q[K_PROT], mx = lp[0];
#pragma unroll
        for (int k = 0; k < K_PROT; k++) { q[k] = lp[k]; mx = fmaxf(mx, q[k]); }
        float den = 0.0f;
#pragma unroll
        for (int k = 0; k < K_PROT; k++) { q[k] = expf(q[k] - mx); den += q[k]; }
#pragma unroll
        for (int k = 0; k < K_PROT; k++) {
            q[k] = q[k] / den;
            g_Q[n*K_PROT + k] = q[k];
            ps[k] += q[k];
        }
    }

    for (int it = 0; it < 3; it++) {
        __syncthreads();
        if (tid < K_PROT) s_col[tid] = 0.0f;
        __syncthreads();
#pragma unroll
        for (int k = 0; k < K_PROT; k++) {
            float v = ps[k];
#pragma unroll
            for (int o = 16; o; o >>= 1) v += __shfl_xor_sync(0xffffffffu, v, o);
            if (lane == 0) atomicAdd(&s_col[k], v);
        }
        __syncthreads();
        float sc[K_PROT];
#pragma unroll
        for (int k = 0; k < K_PROT; k++) sc[k] = s_col[k] + EPSV;

        float nps[K_PROT];
#pragma unroll
        for (int k = 0; k < K_PROT; k++) nps[k] = 0.0f;

        for (int r = tid; r < M; r += 1024) {
            int n = rl[r];
            float q[K_PROT], rs = 0.0f;
#pragma unroll
            for (int k = 0; k < K_PROT; k++) {
                q[k] = g_Q[n*K_PROT + k] / sc[k];
                rs += q[k];
            }
            rs += EPSV;
#pragma unroll
            for (int k = 0; k < K_PROT; k++) {
                q[k] = q[k] / rs;
                g_Q[n*K_PROT + k] = q[k];
                nps[k] += q[k];
            }
            if (it == 2) {
                float best = q[0]; int bi = 0;
#pragma unroll
                for (int k = 1; k < K_PROT; k++)
                    if (q[k] > best) { best = q[k]; bi = k; }
                out_part[n] = (float)bi;
            }
        }
#pragma unroll
        for (int k = 0; k < K_PROT; k++) ps[k] = nps[k];
    }
}

// ---------------- prototype candidates (worklist-driven, 2-deep prefetch) ----------------
__global__ void __launch_bounds__(256) pnew_k(const float* __restrict__ tok) {
    if (blockIdx.x >= g_nw) return;
    int w = g_wl[blockIdx.x];
    int c = w >> 16;
    int start = (w & 0xffff) * PR;
    int M = g_count[c];
    int nr = min(PR, M - start);
    int tid = threadIdx.x;
    __shared__ int   rn[PR];
    __shared__ float qs[PR*K_PROT];

    if (tid < nr) rn[tid] = g_rowlist[c*BN_TOT + start + tid];
    __syncthreads();
    for (int i = tid; i < nr*K_PROT; i += 256) {
        int n = rn[i / K_PROT];
        qs[i] = g_Q[n*K_PROT + (i % K_PROT)] * g_invA[n];
    }
    __syncthreads();

    float acc[3][K_PROT];
#pragma unroll
    for (int j = 0; j < 3; j++)
#pragma unroll
        for (int k = 0; k < K_PROT; k++) acc[j][k] = 0.0f;

    float pf[2][3];
    {
        const float* t0 = tok + (size_t)rn[0]*DIM;
        pf[0][0] = t0[tid]; pf[0][1] = t0[tid+256]; pf[0][2] = t0[tid+512];
    }
    if (nr > 1) {
        const float* t1 = tok + (size_t)rn[1]*DIM;
        pf[1][0] = t1[tid]; pf[1][1] = t1[tid+256]; pf[1][2] = t1[tid+512];
    }
    for (int r = 0; r < nr; r++) {
        float a0 = pf[r&1][0], a1 = pf[r&1][1], a2 = pf[r&1][2];
        if (r + 2 < nr) {
            const float* tq = tok + (size_t)rn[r+2]*DIM;
            pf[r&1][0] = tq[tid]; pf[r&1][1] = tq[tid+256]; pf[r&1][2] = tq[tid+512];
        }
#pragma unroll
        for (int k = 0; k < K_PROT; k++) {
            float q = qs[r*K_PROT + k];
            acc[0][k] += q * a0;
            acc[1][k] += q * a1;
            acc[2][k] += q * a2;
        }
    }
    float* P = g_Pacc + (size_t)c * (K_PROT*DIM);
#pragma unroll
    for (int k = 0; k < K_PROT; k++)
#pragma unroll
        for (int j = 0; j < 3; j++)
            atomicAdd(&P[k*DIM + tid + j*256], acc[j][k]);
}

// ---------------- EMA prototype update ----------------
__global__ void combine_k(const float* __restrict__ proto, float* __restrict__ out_np) {
    int i = blockIdx.x * 256 + threadIdx.x;
    if (i >= SZ_NP) return;
    int c = i / (K_PROT*DIM);
    float p = proto[i];
    out_np[i] = (g_count[c] > 0) ? 0.999f*p + 0.001f*g_Pacc[i] : p;
}

// ---------------- launch ----------------
extern "C" void kernel_launch(void* const* d_in, const int* in_sizes, int n_in,
                              void* d_out, int out_size) {
    const float*    tok    = (const float*)d_in[0];
    const float*    proto  = (const float*)d_in[1];
    const float*    sa     = (const float*)d_in[2];
    const float*    scale  = (const float*)d_in[3];
    const int*      labels = (const int*)d_in[4];
    const unsigned* masks  = (const unsigned*)d_in[5];

    float* out      = (float*)d_out;
    float* out_pp   = out;
    float* out_img  = out_pp  + SZ_PP;
    float* out_cls  = out_img + SZ_IMG;
    float* out_part = out_cls + SZ_CLS;
    float* out_np   = out_part + SZ_PART;
    float* out_pl   = out_np  + SZ_NP;

    const int GEMM_SMEM = STAGES * STG_BYTES;   // 102400
    cudaFuncSetAttribute(gemm_mma, cudaFuncAttributeMaxDynamicSharedMemorySize, GEMM_SMEM);

    zero_k<<<(SZ_NP + 255)/256, 256>>>();
    conv_k<0><<<BN_TOT, 256>>>(tok, BN_TOT);
    conv_k<1><<<NPAD, 256>>>(proto, CK);
    {
        dim3 grid(NPAD/128, BN_TOT/128);   // (8, 128)
        gemm_mma<<<grid, 128, GEMM_SMEM>>>(out_pp);
    }
    mean2<<<(SZ_IMG + 255)/256, 256>>>(out_img);
    cls_logits<<<(SZ_CLS + 255)/256, 256>>>(out_img, sa, scale, out_cls);
    pseudo_k<<<BN_TOT/256, 256>>>(labels, masks, out_pl);
    worklist_k<<<1, 256>>>();
    sinkhorn_k<<<C_CLS, 1024>>>(out_pp, out_part);
    pnew_k<<<768, 256>>>(tok);
    combine_k<<<(SZ_NP + 255)/256, 256>>>(proto, out_np);
}

// round 10
// speedup vs baseline: 1.2820x; 1.2820x over previous
#include <cuda_runtime.h>
#include <cuda_bf16.h>
#include <cstdint>

// ---------------- problem constants ----------------
#define C_CLS   201
#define K_PROT  5
#define DIM     768
#define B_IMG   64
#define NP      256
#define BN_TOT  16384
#define CK      1005
#define NPAD    1024
#define KSPLIT  1536          // stored [hi | lo]; logical K = 2304 via chunk remap
#define EPSV    1e-12f

#define SZ_PP   (BN_TOT*CK)
#define SZ_IMG  (B_IMG*CK)
#define SZ_CLS  (B_IMG*(C_CLS-1))
#define SZ_PART (BN_TOT)
#define SZ_NP   (C_CLS*K_PROT*DIM)

// ---------------- device scratch ----------------
__device__ __nv_bfloat16 g_Abf[(size_t)BN_TOT*KSPLIT];   // 50.3 MB
__device__ __nv_bfloat16 g_Bbf[(size_t)NPAD*KSPLIT];     // 3.1 MB
__device__ float g_invA[BN_TOT];
__device__ int   g_pl[BN_TOT];
__device__ int   g_rowlist[C_CLS*BN_TOT];
__device__ int   g_count[C_CLS];
__device__ float g_Q[BN_TOT*K_PROT];
__device__ float g_colsum[4][C_CLS*K_PROT];
__device__ float g_Pacc[SZ_NP];
__device__ float g_part[128*1024];    // per row-block column sums
__device__ int   g_wl[1024];          // packed (class<<16)|chunk
__device__ int   g_nw;

__device__ __forceinline__ uint32_t smem_u32(const void* p) {
    uint32_t a;
    asm("{ .reg .u64 t; cvta.to.shared.u64 t, %1; cvt.u32.u64 %0, t; }" : "=r"(a) : "l"(p));
    return a;
}

// ---------------- kernel 0: zero scratch ----------------
__global__ void zero_k() {
    int i = blockIdx.x * 256 + threadIdx.x;
    if (i < SZ_NP)  g_Pacc[i] = 0.0f;
    if (i < C_CLS)  g_count[i] = 0;
    if (i < 4*C_CLS*K_PROT) ((float*)g_colsum)[i] = 0.0f;
}

// ---------------- conv: warp-per-row normalize + bf16 hi/lo split ----------------
union B4 { __nv_bfloat162 h[2]; uint2 u; };

template <int MODE>   // 0: tokens -> g_Abf (+g_invA); 1: protos -> g_Bbf
__global__ void __launch_bounds__(256) conv_k(const float* __restrict__ in, int nvalid) {
    int gw = (blockIdx.x * 256 + threadIdx.x) >> 5;
    int lane = threadIdx.x & 31;
    int total = (MODE == 0) ? BN_TOT : NPAD;
    if (gw >= total) return;
    __nv_bfloat16* dst = (MODE == 0 ? g_Abf : g_Bbf) + (size_t)gw * KSPLIT;
    if (MODE == 1 && gw >= nvalid) {
        uint2 z = make_uint2(0u, 0u);
        uint2* d2 = (uint2*)dst;
#pragma unroll
        for (int j = 0; j < 12; j++) d2[lane + j*32] = z;
        return;
    }
    const float4* ip = (const float4*)(in + (size_t)gw * DIM);
    float4 v[6]; float s = 0.0f;
#pragma unroll
    for (int j = 0; j < 6; j++) {
        v[j] = ip[lane + j*32];
        s += v[j].x*v[j].x + v[j].y*v[j].y + v[j].z*v[j].z + v[j].w*v[j].w;
    }
#pragma unroll
    for (int o = 16; o; o >>= 1) s += __shfl_xor_sync(0xffffffffu, s, o);
    float inv = 1.0f / (sqrtf(s) + EPSV);
    if (MODE == 0 && lane == 0) g_invA[gw] = inv;
#pragma unroll
    for (int j = 0; j < 6; j++) {
        int c = 4*lane + 128*j;
        float a0 = v[j].x*inv, a1 = v[j].y*inv, a2 = v[j].z*inv, a3 = v[j].w*inv;
        B4 hi, lo;
        hi.h[0] = __float22bfloat162_rn(make_float2(a0, a1));
        hi.h[1] = __float22bfloat162_rn(make_float2(a2, a3));
        lo.h[0] = __float22bfloat162_rn(make_float2(a0 - __bfloat162float(__low2bfloat16(hi.h[0])),
                                                   a1 - __bfloat162float(__high2bfloat16(hi.h[0]))));
        lo.h[1] = __float22bfloat162_rn(make_float2(a2 - __bfloat162float(__low2bfloat16(hi.h[1])),
                                                   a3 - __bfloat162float(__high2bfloat16(hi.h[1]))));
        *(uint2*)(dst + c)       = hi.u;
        *(uint2*)(dst + 768 + c) = lo.u;
    }
}

// ---------------- GEMM: mma.sync bf16, CTA 128x128, logical K=2304 (round-8) ----------------
#define NSTAGE  72
#define STAGES  4
#define STG_BYTES 20480

__device__ __forceinline__ void ldsm4(uint32_t& r0, uint32_t& r1, uint32_t& r2, uint32_t& r3,
                                      uint32_t addr) {
    asm volatile("ldmatrix.sync.aligned.m8n8.x4.shared.b16 {%0,%1,%2,%3}, [%4];"
                 : "=r"(r0), "=r"(r1), "=r"(r2), "=r"(r3) : "r"(addr));
}
__device__ __forceinline__ void mma16816(float* c, const uint32_t* a, const uint32_t* b) {
    asm volatile("mma.sync.aligned.m16n8k16.row.col.f32.bf16.bf16.f32 "
                 "{%0,%1,%2,%3}, {%4,%5,%6,%7}, {%8,%9}, {%0,%1,%2,%3};"
                 : "+f"(c[0]), "+f"(c[1]), "+f"(c[2]), "+f"(c[3])
                 : "r"(a[0]), "r"(a[1]), "r"(a[2]), "r"(a[3]), "r"(b[0]), "r"(b[1]));
}
__device__ __forceinline__ void cpa16(uint32_t dst, const void* src) {
    asm volatile("cp.async.cg.shared.global [%0], [%1], 16;" :: "r"(dst), "l"(src));
}

__global__ void __launch_bounds__(128, 2) gemm_mma(float* __restrict__ Cout) {
    extern __shared__ char sm[];

    int tid = threadIdx.x;
    int lane = tid & 31;
    int warp = tid >> 5;
    int wm = warp & 1;
    int wn = warp >> 1;
    int row0 = blockIdx.y * 128;
    int col0 = blockIdx.x * 128;

    uint32_t sbase = smem_u32(sm);
    const char* gA = (const char*)g_Abf + (size_t)(row0 + tid) * (KSPLIT*2);
    const char* gB = (const char*)g_Bbf + (size_t)(col0 + tid) * (KSPLIT*2);

    uint32_t a_lane = (uint32_t)((((lane >> 3) & 1)*8 + (lane & 7))*80 + ((lane >> 4) & 1)*16);
    uint32_t b_lane = (uint32_t)((((lane >> 4) & 1)*8 + (lane & 7))*80 + ((lane >> 3) & 1)*16);
    uint32_t a_off = (uint32_t)(wm*64)*80 + a_lane;
    uint32_t b_off = 10240u + (uint32_t)(wn*64)*80 + b_lane;

    float acc[4][8][4];
#pragma unroll
    for (int i = 0; i < 4; i++)
#pragma unroll
        for (int j = 0; j < 8; j++)
#pragma unroll
            for (int r = 0; r < 4; r++) acc[i][j][r] = 0.0f;

#pragma unroll
    for (int p = 0; p < STAGES - 1; p++) {
        uint32_t dA = sbase + p*STG_BYTES + tid*80;
        const char* pA = gA + p*64;
        const char* pB = gB + p*64;
#pragma unroll
        for (int c = 0; c < 4; c++) {
            cpa16(dA + c*16, pA + c*16);
            cpa16(dA + 10240 + c*16, pB + c*16);
        }
        asm volatile("cp.async.commit_group;" ::: "memory");
    }

    for (int s = 0; s < NSTAGE; s++) {
        asm volatile("cp.async.wait_group 2;" ::: "memory");
        __syncthreads();
        uint32_t stg = sbase + (uint32_t)(s & 3)*STG_BYTES;
        uint32_t ab = stg + a_off;
        uint32_t bb = stg + b_off;
#pragma unroll
        for (int ks = 0; ks < 2; ks++) {
            uint32_t af[4][4], bf[4][4];
#pragma unroll
            for (int i = 0; i < 4; i++)
                ldsm4(af[i][0], af[i][1], af[i][2], af[i][3], ab + ks*32 + i*16*80);
#pragma unroll
            for (int j = 0; j < 4; j++)
                ldsm4(bf[j][0], bf[j][1], bf[j][2], bf[j][3], bb + ks*32 + j*16*80);
#pragma unroll
            for (int im = 0; im < 4; im++)
#pragma unroll
                for (int j = 0; j < 4; j++) {
                    mma16816(acc[im][2*j],   af[im], &bf[j][0]);
                    mma16816(acc[im][2*j+1], af[im], &bf[j][2]);
                }
        }
        if (s + STAGES - 1 < NSTAGE) {
            int p = s + STAGES - 1;
            int pa = (p < 24) ? p : (p - 24);
            int pb = (p < 48) ? p : (p - 48);
            uint32_t dA = sbase + (uint32_t)(p & 3)*STG_BYTES + tid*80;
            const char* pA = gA + pa*64;
            const char* pB = gB + pb*64;
#pragma unroll
            for (int c = 0; c < 4; c++) {
                cpa16(dA + c*16, pA + c*16);
                cpa16(dA + 10240 + c*16, pB + c*16);
            }
        }
        asm volatile("cp.async.commit_group;" ::: "memory");
    }

    // fused patch-mean partials
    float cs[16];
#pragma unroll
    for (int j = 0; j < 8; j++)
#pragma unroll
        for (int h = 0; h < 2; h++) {
            float v = 0.0f;
#pragma unroll
            for (int im = 0; im < 4; im++) v += acc[im][j][h] + acc[im][j][h+2];
            cs[j*2+h] = v;
        }
#pragma unroll
    for (int o = 4; o <= 16; o <<= 1)
#pragma unroll
        for (int t = 0; t < 16; t++) cs[t] += __shfl_xor_sync(0xffffffffu, cs[t], o);

    __syncthreads();
    float* scol = (float*)sm;
    if (lane < 4) {
#pragma unroll
        for (int j = 0; j < 8; j++) {
            scol[wm*128 + wn*64 + lane*2 + j*8]     = cs[j*2];
            scol[wm*128 + wn*64 + lane*2 + j*8 + 1] = cs[j*2+1];
        }
    }
    __syncthreads();
    if (tid < 128)
        g_part[blockIdx.y*1024 + col0 + tid] = scol[tid] + scol[128 + tid];

    // epilogue: scalar stores
    int mb = row0 + wm*64 + (lane >> 2);
    int nb0 = col0 + wn*64 + (lane & 3)*2;
#pragma unroll
    for (int im = 0; im < 4; im++) {
        size_t r0 = (size_t)(mb + im*16) * CK;
        size_t r1 = (size_t)(mb + im*16 + 8) * CK;
#pragma unroll
        for (int j = 0; j < 8; j++) {
            int n = nb0 + j*8;
            if (n < CK) {
                Cout[r0 + n] = acc[im][j][0];
                Cout[r1 + n] = acc[im][j][2];
            }
            if (n + 1 < CK) {
                Cout[r0 + n + 1] = acc[im][j][1];
                Cout[r1 + n + 1] = acc[im][j][3];
            }
        }
    }
}

// ---------------- combine partial sums -> image logits ----------------
__global__ void mean2(float* __restrict__ img) {
    int idx = blockIdx.x * 256 + threadIdx.x;
    if (idx >= SZ_IMG) return;
    int b = idx / CK, ck = idx % CK;
    img[idx] = (g_part[(2*b)*1024 + ck] + g_part[(2*b+1)*1024 + ck]) * (1.0f/256.0f);
}

// ---------------- class logits ----------------
__global__ void cls_logits(const float* __restrict__ img, const float* __restrict__ sa,
                           const float* __restrict__ scale_p, float* __restrict__ out) {
    int idx = blockIdx.x * 256 + threadIdx.x;
    if (idx >= SZ_CLS) return;
    int b = idx / (C_CLS-1), c = idx % (C_CLS-1);
    float s[K_PROT], mx = -1e30f;
#pragma unroll
    for (int k = 0; k < K_PROT; k++) { s[k] = sa[c*K_PROT + k]; mx = fmaxf(mx, s[k]); }
    float den = 0.0f;
#pragma unroll
    for (int k = 0; k < K_PROT; k++) { s[k] = expf(s[k] - mx); den += s[k]; }
    float scale = scale_p[0];
    float acc = 0.0f;
#pragma unroll
    for (int k = 0; k < K_PROT; k++)
        acc += scale * img[b*CK + c*K_PROT + k] * (s[k] / den * (float)K_PROT);
    out[idx] = acc;
}

// ---------------- Sinkhorn init: pseudo labels + rowlist + softmax + colsum0 ----------------
__global__ void __launch_bounds__(256) sk_init(const float* __restrict__ L,
                                               const int* __restrict__ labels,
                                               const unsigned* __restrict__ masks,
                                               float* __restrict__ out_pl) {
    int bn = blockIdx.x * 256 + threadIdx.x;
    int lab = labels[bn >> 8];            // uniform within warp (256 | image)
    bool fg = (masks[bn] != 0u);
    int pl = fg ? lab : (C_CLS - 1);
    g_pl[bn] = pl;
    out_pl[bn] = (float)pl;
    int pos = atomicAdd(&g_count[pl], 1);
    g_rowlist[pl*BN_TOT + pos] = bn;

    const float* lp = L + (size_t)bn*CK + pl*K_PROT;
    float q[K_PROT], mx = lp[0];
#pragma unroll
    for (int k = 0; k < K_PROT; k++) { q[k] = lp[k]; mx = fmaxf(mx, q[k]); }
    float den = 0.0f;
#pragma unroll
    for (int k = 0; k < K_PROT; k++) { q[k] = expf(q[k] - mx); den += q[k]; }
    float sf[K_PROT], sb[K_PROT];
#pragma unroll
    for (int k = 0; k < K_PROT; k++) {
        q[k] = q[k] / den;
        g_Q[bn*K_PROT + k] = q[k];
        sf[k] = fg ? q[k] : 0.0f;
        sb[k] = fg ? 0.0f : q[k];
    }
#pragma unroll
    for (int o = 16; o; o >>= 1)
#pragma unroll
        for (int k = 0; k < K_PROT; k++) {
            sf[k] += __shfl_xor_sync(0xffffffffu, sf[k], o);
            sb[k] += __shfl_xor_sync(0xffffffffu, sb[k], o);
        }
    if ((threadIdx.x & 31) == 0) {
#pragma unroll
        for (int k = 0; k < K_PROT; k++) {
            atomicAdd(&g_colsum[0][lab*K_PROT + k], sf[k]);
            atomicAdd(&g_colsum[0][(C_CLS-1)*K_PROT + k], sb[k]);
        }
    }
}

// ---------------- Sinkhorn iteration (row-parallel) ----------------
template <int IT>
__global__ void __launch_bounds__(256) sk_iter(const int* __restrict__ labels,
                                               float* __restrict__ out_part) {
    int bn = blockIdx.x * 256 + threadIdx.x;
    int lab = labels[bn >> 8];
    int pl = g_pl[bn];
    bool fg = (pl == lab);

    float q[K_PROT], rs = 0.0f;
#pragma unroll
    for (int k = 0; k < K_PROT; k++) {
        float cs = g_colsum[IT][pl*K_PROT + k] + EPSV;
        q[k] = g_Q[bn*K_PROT + k] / cs;
        rs += q[k];
    }
    rs += EPSV;
#pragma unroll
    for (int k = 0; k < K_PROT; k++) {
        q[k] = q[k] / rs;
        g_Q[bn*K_PROT + k] = q[k];
    }
    if (IT < 2) {
        float sf[K_PROT], sb[K_PROT];
#pragma unroll
        for (int k = 0; k < K_PROT; k++) {
            sf[k] = fg ? q[k] : 0.0f;
            sb[k] = fg ? 0.0f : q[k];
        }
#pragma unroll
        for (int o = 16; o; o >>= 1)
#pragma unroll
            for (int k = 0; k < K_PROT; k++) {
                sf[k] += __shfl_xor_sync(0xffffffffu, sf[k], o);
                sb[k] += __shfl_xor_sync(0xffffffffu, sb[k], o);
            }
        if ((threadIdx.x & 31) == 0) {
#pragma unroll
            for (int k = 0; k < K_PROT; k++) {
                atomicAdd(&g_colsum[IT+1][lab*K_PROT + k], sf[k]);
                atomicAdd(&g_colsum[IT+1][(C_CLS-1)*K_PROT + k], sb[k]);
            }
        }
    } else {
        float best = q[0]; int bi = 0;
#pragma unroll
        for (int k = 1; k < K_PROT; k++)
            if (q[k] > best) { best = q[k]; bi = k; }
        out_part[bn] = (float)bi;
    }
}

// ---------------- worklist: compact (class, chunk) pairs ----------------
#define PR 32
__global__ void worklist_k() {
    __shared__ int sc[256];
    int tid = threadIdx.x;
    int n = (tid < C_CLS) ? (g_count[tid] + PR - 1) / PR : 0;
    sc[tid] = n;
    __syncthreads();
    for (int off = 1; off < 256; off <<= 1) {
        int v = (tid >= off) ? sc[tid - off] : 0;
        __syncthreads();
        sc[tid] += v;
        __syncthreads();
    }
    int end = sc[tid];
    int start = end - n;
    for (int i = 0; i < n; i++) g_wl[start + i] = (tid << 16) | i;
    if (tid == 255) g_nw = sc[255];
}

// ---------------- prototype candidates (worklist-driven, 2-deep prefetch) ----------------
__global__ void __launch_bounds__(256) pnew_k(const float* __restrict__ tok) {
    if (blockIdx.x >= g_nw) return;
    int w = g_wl[blockIdx.x];
    int c = w >> 16;
    int start = (w & 0xffff) * PR;
    int M = g_count[c];
    int nr = min(PR, M - start);
    int tid = threadIdx.x;
    __shared__ int   rn[PR];
    __shared__ float qs[PR*K_PROT];

    if (tid < nr) rn[tid] = g_rowlist[c*BN_TOT + start + tid];
    __syncthreads();
    for (int i = tid; i < nr*K_PROT; i += 256) {
        int n = rn[i / K_PROT];
        qs[i] = g_Q[n*K_PROT + (i % K_PROT)] * g_invA[n];
    }
    __syncthreads();

    float acc[3][K_PROT];
#pragma unroll
    for (int j = 0; j < 3; j++)
#pragma unroll
        for (int k = 0; k < K_PROT; k++) acc[j][k] = 0.0f;

    float pf[2][3];
    {
        const float* t0 = tok + (size_t)rn[0]*DIM;
        pf[0][0] = t0[tid]; pf[0][1] = t0[tid+256]; pf[0][2] = t0[tid+512];
    }
    if (nr > 1) {
        const float* t1 = tok + (size_t)rn[1]*DIM;
        pf[1][0] = t1[tid]; pf[1][1] = t1[tid+256]; pf[1][2] = t1[tid+512];
    }
    for (int r = 0; r < nr; r++) {
        float a0 = pf[r&1][0], a1 = pf[r&1][1], a2 = pf[r&1][2];
        if (r + 2 < nr) {
            const float* tq = tok + (size_t)rn[r+2]*DIM;
            pf[r&1][0] = tq[tid]; pf[r&1][1] = tq[tid+256]; pf[r&1][2] = tq[tid+512];
        }
#pragma unroll
        for (int k = 0; k < K_PROT; k++) {
            float q = qs[r*K_PROT + k];
            acc[0][k] += q * a0;
            acc[1][k] += q * a1;
            acc[2][k] += q * a2;
        }
    }
    float* P = g_Pacc + (size_t)c * (K_PROT*DIM);
#pragma unroll
    for (int k = 0; k < K_PROT; k++)
#pragma unroll
        for (int j = 0; j < 3; j++)
            atomicAdd(&P[k*DIM + tid + j*256], acc[j][k]);
}

// ---------------- EMA prototype update ----------------
__global__ void combine_k(const float* __restrict__ proto, float* __restrict__ out_np) {
    int i = blockIdx.x * 256 + threadIdx.x;
    if (i >= SZ_NP) return;
    int c = i / (K_PROT*DIM);
    float p = proto[i];
    out_np[i] = (g_count[c] > 0) ? 0.999f*p + 0.001f*g_Pacc[i] : p;
}

// ---------------- launch ----------------
extern "C" void kernel_launch(void* const* d_in, const int* in_sizes, int n_in,
                              void* d_out, int out_size) {
    const float*    tok    = (const float*)d_in[0];
    const float*    proto  = (const float*)d_in[1];
    const float*    sa     = (const float*)d_in[2];
    const float*    scale  = (const float*)d_in[3];
    const int*      labels = (const int*)d_in[4];
    const unsigned* masks  = (const unsigned*)d_in[5];

    float* out      = (float*)d_out;
    float* out_pp   = out;
    float* out_img  = out_pp  + SZ_PP;
    float* out_cls  = out_img + SZ_IMG;
    float* out_part = out_cls + SZ_CLS;
    float* out_np   = out_part + SZ_PART;
    float* out_pl   = out_np  + SZ_NP;

    const int GEMM_SMEM = STAGES * STG_BYTES;   // 81920
    cudaFuncSetAttribute(gemm_mma, cudaFuncAttributeMaxDynamicSharedMemorySize, GEMM_SMEM);

    zero_k<<<(SZ_NP + 255)/256, 256>>>();
    conv_k<0><<<BN_TOT*32/256, 256>>>(tok, BN_TOT);
    conv_k<1><<<NPAD*32/256, 256>>>(proto, CK);
    {
        dim3 grid(NPAD/128, BN_TOT/128);   // (8, 128)
        gemm_mma<<<grid, 128, GEMM_SMEM>>>(out_pp);
    }
    mean2<<<(SZ_IMG + 255)/256, 256>>>(out_img);
    cls_logits<<<(SZ_CLS + 255)/256, 256>>>(out_img, sa, scale, out_cls);
    sk_init<<<BN_TOT/256, 256>>>(out_pp, labels, masks, out_pl);
    worklist_k<<<1, 256>>>();
    sk_iter<0><<<BN_TOT/256, 256>>>(labels, out_part);
    sk_iter<1><<<BN_TOT/256, 256>>>(labels, out_part);
    sk_iter<2><<<BN_TOT/256, 256>>>(labels, out_part);
    pnew_k<<<768, 256>>>(tok);
    combine_k<<<(SZ_NP + 255)/256, 256>>>(proto, out_np);
}

// round 11
// speedup vs baseline: 1.3552x; 1.0571x over previous
#include <cuda_runtime.h>
#include <cuda_bf16.h>
#include <cstdint>

// ---------------- problem constants ----------------
#define C_CLS   201
#define K_PROT  5
#define DIM     768
#define B_IMG   64
#define NP      256
#define BN_TOT  16384
#define CK      1005
#define NPAD    1024
#define KSPLIT  2304          // duplicated: A'=[Ah|Ah|Al], B'=[Bh|Bl|Bh]
#define EPSV    1e-12f

#define SZ_PP   (BN_TOT*CK)
#define SZ_IMG  (B_IMG*CK)
#define SZ_CLS  (B_IMG*(C_CLS-1))
#define SZ_PART (BN_TOT)
#define SZ_NP   (C_CLS*K_PROT*DIM)

// ---------------- device scratch ----------------
__device__ __nv_bfloat16 g_Abf[(size_t)BN_TOT*KSPLIT];   // 75.5 MB
__device__ __nv_bfloat16 g_Bbf[(size_t)NPAD*KSPLIT];     // 4.7 MB
__device__ float g_invA[BN_TOT];
__device__ int   g_pl[BN_TOT];
__device__ int   g_rowlist[C_CLS*BN_TOT];
__device__ int   g_count[C_CLS];
__device__ float g_Q[BN_TOT*K_PROT];
__device__ float g_colsum[4][C_CLS*K_PROT];
__device__ float g_Pacc[SZ_NP];
__device__ float g_part[128*1024];    // per row-block column sums
__device__ int   g_wl[1024];          // packed (class<<16)|chunk
__device__ int   g_nw;

__device__ __forceinline__ uint32_t smem_u32(const void* p) {
    uint32_t a;
    asm("{ .reg .u64 t; cvta.to.shared.u64 t, %1; cvt.u32.u64 %0, t; }" : "=r"(a) : "l"(p));
    return a;
}

// ---------------- kernel 0: zero scratch ----------------
__global__ void zero_k() {
    int i = blockIdx.x * 256 + threadIdx.x;
    if (i < SZ_NP)  g_Pacc[i] = 0.0f;
    if (i < C_CLS)  g_count[i] = 0;
    if (i < 4*C_CLS*K_PROT) ((float*)g_colsum)[i] = 0.0f;
}

// ---------------- conv: warp-per-row normalize + bf16 hi/lo split (duplicated) ----------------
union B4 { __nv_bfloat162 h[2]; uint2 u; };

template <int MODE>   // 0: tokens -> g_Abf (+g_invA); 1: protos -> g_Bbf
__global__ void __launch_bounds__(256) conv_k(const float* __restrict__ in, int nvalid) {
    int gw = (blockIdx.x * 256 + threadIdx.x) >> 5;
    int lane = threadIdx.x & 31;
    int total = (MODE == 0) ? BN_TOT : NPAD;
    if (gw >= total) return;
    __nv_bfloat16* dst = (MODE == 0 ? g_Abf : g_Bbf) + (size_t)gw * KSPLIT;
    if (MODE == 1 && gw >= nvalid) {
        uint2 z = make_uint2(0u, 0u);
        uint2* d2 = (uint2*)dst;
#pragma unroll
        for (int j = 0; j < 18; j++) d2[lane + j*32] = z;
        return;
    }
    const float4* ip = (const float4*)(in + (size_t)gw * DIM);
    float4 v[6]; float s = 0.0f;
#pragma unroll
    for (int j = 0; j < 6; j++) {
        v[j] = ip[lane + j*32];
        s += v[j].x*v[j].x + v[j].y*v[j].y + v[j].z*v[j].z + v[j].w*v[j].w;
    }
#pragma unroll
    for (int o = 16; o; o >>= 1) s += __shfl_xor_sync(0xffffffffu, s, o);
    float inv = 1.0f / (sqrtf(s) + EPSV);
    if (MODE == 0 && lane == 0) g_invA[gw] = inv;
#pragma unroll
    for (int j = 0; j < 6; j++) {
        int c = 4*lane + 128*j;
        float a0 = v[j].x*inv, a1 = v[j].y*inv, a2 = v[j].z*inv, a3 = v[j].w*inv;
        B4 hi, lo;
        hi.h[0] = __float22bfloat162_rn(make_float2(a0, a1));
        hi.h[1] = __float22bfloat162_rn(make_float2(a2, a3));
        lo.h[0] = __float22bfloat162_rn(make_float2(a0 - __bfloat162float(__low2bfloat16(hi.h[0])),
                                                   a1 - __bfloat162float(__high2bfloat16(hi.h[0]))));
        lo.h[1] = __float22bfloat162_rn(make_float2(a2 - __bfloat162float(__low2bfloat16(hi.h[1])),
                                                   a3 - __bfloat162float(__high2bfloat16(hi.h[1]))));
        if (MODE == 0) {   // A' = [hi | hi | lo]
            *(uint2*)(dst + c)        = hi.u;
            *(uint2*)(dst + 768 + c)  = hi.u;
            *(uint2*)(dst + 1536 + c) = lo.u;
        } else {           // B' = [hi | lo | hi]
            *(uint2*)(dst + c)        = hi.u;
            *(uint2*)(dst + 768 + c)  = lo.u;
            *(uint2*)(dst + 1536 + c) = hi.u;
        }
    }
}

// ---------------- GEMM: mma.sync bf16, CTA 128x128, K=2304, linear prefetch ----------------
#define NSTAGE  72
#define STAGES  4
#define STG_BYTES 20480

__device__ __forceinline__ void ldsm4(uint32_t& r0, uint32_t& r1, uint32_t& r2, uint32_t& r3,
                                      uint32_t addr) {
    asm volatile("ldmatrix.sync.aligned.m8n8.x4.shared.b16 {%0,%1,%2,%3}, [%4];"
                 : "=r"(r0), "=r"(r1), "=r"(r2), "=r"(r3) : "r"(addr));
}
__device__ __forceinline__ void mma16816(float* c, const uint32_t* a, const uint32_t* b) {
    asm volatile("mma.sync.aligned.m16n8k16.row.col.f32.bf16.bf16.f32 "
                 "{%0,%1,%2,%3}, {%4,%5,%6,%7}, {%8,%9}, {%0,%1,%2,%3};"
                 : "+f"(c[0]), "+f"(c[1]), "+f"(c[2]), "+f"(c[3])
                 : "r"(a[0]), "r"(a[1]), "r"(a[2]), "r"(a[3]), "r"(b[0]), "r"(b[1]));
}
__device__ __forceinline__ void cpa16(uint32_t dst, const void* src) {
    asm volatile("cp.async.cg.shared.global [%0], [%1], 16;" :: "r"(dst), "l"(src));
}

__global__ void __launch_bounds__(128, 2) gemm_mma(float* __restrict__ Cout) {
    extern __shared__ char sm[];

    int tid = threadIdx.x;
    int lane = tid & 31;
    int warp = tid >> 5;
    int wm = warp & 1;
    int wn = warp >> 1;
    int row0 = blockIdx.y * 128;
    int col0 = blockIdx.x * 128;

    uint32_t sbase = smem_u32(sm);
    const char* gA = (const char*)g_Abf + (size_t)(row0 + tid) * (KSPLIT*2);
    const char* gB = (const char*)g_Bbf + (size_t)(col0 + tid) * (KSPLIT*2);

    uint32_t a_lane = (uint32_t)((((lane >> 3) & 1)*8 + (lane & 7))*80 + ((lane >> 4) & 1)*16);
    uint32_t b_lane = (uint32_t)((((lane >> 4) & 1)*8 + (lane & 7))*80 + ((lane >> 3) & 1)*16);
    uint32_t a_off = (uint32_t)(wm*64)*80 + a_lane;
    uint32_t b_off = 10240u + (uint32_t)(wn*64)*80 + b_lane;

    float acc[4][8][4];
#pragma unroll
    for (int i = 0; i < 4; i++)
#pragma unroll
        for (int j = 0; j < 8; j++)
#pragma unroll
            for (int r = 0; r < 4; r++) acc[i][j][r] = 0.0f;

#pragma unroll
    for (int p = 0; p < STAGES - 1; p++) {
        uint32_t dA = sbase + p*STG_BYTES + tid*80;
        const char* pA = gA + p*64;
        const char* pB = gB + p*64;
#pragma unroll
        for (int c = 0; c < 4; c++) {
            cpa16(dA + c*16, pA + c*16);
            cpa16(dA + 10240 + c*16, pB + c*16);
        }
        asm volatile("cp.async.commit_group;" ::: "memory");
    }

    for (int s = 0; s < NSTAGE; s++) {
        asm volatile("cp.async.wait_group 2;" ::: "memory");
        __syncthreads();
        uint32_t stg = sbase + (uint32_t)(s & 3)*STG_BYTES;
        uint32_t ab = stg + a_off;
        uint32_t bb = stg + b_off;
#pragma unroll
        for (int ks = 0; ks < 2; ks++) {
            uint32_t af[4][4], bf[4][4];
#pragma unroll
            for (int i = 0; i < 4; i++)
                ldsm4(af[i][0], af[i][1], af[i][2], af[i][3], ab + ks*32 + i*16*80);
#pragma unroll
            for (int j = 0; j < 4; j++)
                ldsm4(bf[j][0], bf[j][1], bf[j][2], bf[j][3], bb + ks*32 + j*16*80);
#pragma unroll
            for (int im = 0; im < 4; im++)
#pragma unroll
                for (int j = 0; j < 4; j++) {
                    mma16816(acc[im][2*j],   af[im], &bf[j][0]);
                    mma16816(acc[im][2*j+1], af[im], &bf[j][2]);
                }
        }
        if (s + STAGES - 1 < NSTAGE) {
            int p = s + STAGES - 1;
            uint32_t dA = sbase + (uint32_t)(p & 3)*STG_BYTES + tid*80;
            const char* pA = gA + p*64;
            const char* pB = gB + p*64;
#pragma unroll
            for (int c = 0; c < 4; c++) {
                cpa16(dA + c*16, pA + c*16);
                cpa16(dA + 10240 + c*16, pB + c*16);
            }
        }
        asm volatile("cp.async.commit_group;" ::: "memory");
    }

    // fused patch-mean partials
    float cs[16];
#pragma unroll
    for (int j = 0; j < 8; j++)
#pragma unroll
        for (int h = 0; h < 2; h++) {
            float v = 0.0f;
#pragma unroll
            for (int im = 0; im < 4; im++) v += acc[im][j][h] + acc[im][j][h+2];
            cs[j*2+h] = v;
        }
#pragma unroll
    for (int o = 4; o <= 16; o <<= 1)
#pragma unroll
        for (int t = 0; t < 16; t++) cs[t] += __shfl_xor_sync(0xffffffffu, cs[t], o);

    __syncthreads();
    float* scol = (float*)sm;
    if (lane < 4) {
#pragma unroll
        for (int j = 0; j < 8; j++) {
            scol[wm*128 + wn*64 + lane*2 + j*8]     = cs[j*2];
            scol[wm*128 + wn*64 + lane*2 + j*8 + 1] = cs[j*2+1];
        }
    }
    __syncthreads();
    if (tid < 128)
        g_part[blockIdx.y*1024 + col0 + tid] = scol[tid] + scol[128 + tid];

    // epilogue: scalar stores (CK=1005 odd -> rows not 8B aligned)
    int mb = row0 + wm*64 + (lane >> 2);
    int nb0 = col0 + wn*64 + (lane & 3)*2;
#pragma unroll
    for (int im = 0; im < 4; im++) {
        size_t r0 = (size_t)(mb + im*16) * CK;
        size_t r1 = (size_t)(mb + im*16 + 8) * CK;
#pragma unroll
        for (int j = 0; j < 8; j++) {
            int n = nb0 + j*8;
            if (n < CK) {
                Cout[r0 + n] = acc[im][j][0];
                Cout[r1 + n] = acc[im][j][2];
            }
            if (n + 1 < CK) {
                Cout[r0 + n + 1] = acc[im][j][1];
                Cout[r1 + n + 1] = acc[im][j][3];
            }
        }
    }
}

// ---------------- combine partial sums -> image logits ----------------
__global__ void mean2(float* __restrict__ img) {
    int idx = blockIdx.x * 256 + threadIdx.x;
    if (idx >= SZ_IMG) return;
    int b = idx / CK, ck = idx % CK;
    img[idx] = (g_part[(2*b)*1024 + ck] + g_part[(2*b+1)*1024 + ck]) * (1.0f/256.0f);
}

// ---------------- class logits ----------------
__global__ void cls_logits(const float* __restrict__ img, const float* __restrict__ sa,
                           const float* __restrict__ scale_p, float* __restrict__ out) {
    int idx = blockIdx.x * 256 + threadIdx.x;
    if (idx >= SZ_CLS) return;
    int b = idx / (C_CLS-1), c = idx % (C_CLS-1);
    float s[K_PROT], mx = -1e30f;
#pragma unroll
    for (int k = 0; k < K_PROT; k++) { s[k] = sa[c*K_PROT + k]; mx = fmaxf(mx, s[k]); }
    float den = 0.0f;
#pragma unroll
    for (int k = 0; k < K_PROT; k++) { s[k] = expf(s[k] - mx); den += s[k]; }
    float scale = scale_p[0];
    float acc = 0.0f;
#pragma unroll
    for (int k = 0; k < K_PROT; k++)
        acc += scale * img[b*CK + c*K_PROT + k] * (s[k] / den * (float)K_PROT);
    out[idx] = acc;
}

// ---------------- Sinkhorn init: pseudo labels + rowlist + softmax + colsum0 ----------------
__global__ void __launch_bounds__(256) sk_init(const float* __restrict__ L,
                                               const int* __restrict__ labels,
                                               const unsigned* __restrict__ masks,
                                               float* __restrict__ out_pl) {
    int bn = blockIdx.x * 256 + threadIdx.x;
    int lab = labels[bn >> 8];            // uniform within warp (256 | image)
    bool fg = (masks[bn] != 0u);
    int pl = fg ? lab : (C_CLS - 1);
    g_pl[bn] = pl;
    out_pl[bn] = (float)pl;
    int pos = atomicAdd(&g_count[pl], 1);
    g_rowlist[pl*BN_TOT + pos] = bn;

    const float* lp = L + (size_t)bn*CK + pl*K_PROT;
    float q[K_PROT], mx = lp[0];
#pragma unroll
    for (int k = 0; k < K_PROT; k++) { q[k] = lp[k]; mx = fmaxf(mx, q[k]); }
    float den = 0.0f;
#pragma unroll
    for (int k = 0; k < K_PROT; k++) { q[k] = expf(q[k] - mx); den += q[k]; }
    float sf[K_PROT], sb[K_PROT];
#pragma unroll
    for (int k = 0; k < K_PROT; k++) {
        q[k] = q[k] / den;
        g_Q[bn*K_PROT + k] = q[k];
        sf[k] = fg ? q[k] : 0.0f;
        sb[k] = fg ? 0.0f : q[k];
    }
#pragma unroll
    for (int o = 16; o; o >>= 1)
#pragma unroll
        for (int k = 0; k < K_PROT; k++) {
            sf[k] += __shfl_xor_sync(0xffffffffu, sf[k], o);
            sb[k] += __shfl_xor_sync(0xffffffffu, sb[k], o);
        }
    if ((threadIdx.x & 31) == 0) {
#pragma unroll
        for (int k = 0; k < K_PROT; k++) {
            atomicAdd(&g_colsum[0][lab*K_PROT + k], sf[k]);
            atomicAdd(&g_colsum[0][(C_CLS-1)*K_PROT + k], sb[k]);
        }
    }
}

// ---------------- Sinkhorn iteration (row-parallel) ----------------
template <int IT>
__global__ void __launch_bounds__(256) sk_iter(const int* __restrict__ labels,
                                               float* __restrict__ out_part) {
    int bn = blockIdx.x * 256 + threadIdx.x;
    int lab = labels[bn >> 8];
    int pl = g_pl[bn];
    bool fg = (pl == lab);

    float q[K_PROT], rs = 0.0f;
#pragma unroll
    for (int k = 0; k < K_PROT; k++) {
        float cs = g_colsum[IT][pl*K_PROT + k] + EPSV;
        q[k] = g_Q[bn*K_PROT + k] / cs;
        rs += q[k];
    }
    rs += EPSV;
#pragma unroll
    for (int k = 0; k < K_PROT; k++) {
        q[k] = q[k] / rs;
        g_Q[bn*K_PROT + k] = q[k];
    }
    if (IT < 2) {
        float sf[K_PROT], sb[K_PROT];
#pragma unroll
        for (int k = 0; k < K_PROT; k++) {
            sf[k] = fg ? q[k] : 0.0f;
            sb[k] = fg ? 0.0f : q[k];
        }
#pragma unroll
        for (int o = 16; o; o >>= 1)
#pragma unroll
            for (int k = 0; k < K_PROT; k++) {
                sf[k] += __shfl_xor_sync(0xffffffffu, sf[k], o);
                sb[k] += __shfl_xor_sync(0xffffffffu, sb[k], o);
            }
        if ((threadIdx.x & 31) == 0) {
#pragma unroll
            for (int k = 0; k < K_PROT; k++) {
                atomicAdd(&g_colsum[IT+1][lab*K_PROT + k], sf[k]);
                atomicAdd(&g_colsum[IT+1][(C_CLS-1)*K_PROT + k], sb[k]);
            }
        }
    } else {
        float best = q[0]; int bi = 0;
#pragma unroll
        for (int k = 1; k < K_PROT; k++)
            if (q[k] > best) { best = q[k]; bi = k; }
        out_part[bn] = (float)bi;
    }
}

// ---------------- worklist: compact (class, chunk) pairs ----------------
#define PR 32
__global__ void worklist_k() {
    __shared__ int sc[256];
    int tid = threadIdx.x;
    int n = (tid < C_CLS) ? (g_count[tid] + PR - 1) / PR : 0;
    sc[tid] = n;
    __syncthreads();
    for (int off = 1; off < 256; off <<= 1) {
        int v = (tid >= off) ? sc[tid - off] : 0;
        __syncthreads();
        sc[tid] += v;
        __syncthreads();
    }
    int end = sc[tid];
    int start = end - n;
    for (int i = 0; i < n; i++) g_wl[start + i] = (tid << 16) | i;
    if (tid == 255) g_nw = sc[255];
}

// ---------------- prototype candidates (worklist-driven, 2-deep prefetch) ----------------
__global__ void __launch_bounds__(256) pnew_k(const float* __restrict__ tok) {
    if (blockIdx.x >= g_nw) return;
    int w = g_wl[blockIdx.x];
    int c = w >> 16;
    int start = (w & 0xffff) * PR;
    int M = g_count[c];
    int nr = min(PR, M - start);
    int tid = threadIdx.x;
    __shared__ int   rn[PR];
    __shared__ float qs[PR*K_PROT];

    if (tid < nr) rn[tid] = g_rowlist[c*BN_TOT + start + tid];
    __syncthreads();
    for (int i = tid; i < nr*K_PROT; i += 256) {
        int n = rn[i / K_PROT];
        qs[i] = g_Q[n*K_PROT + (i % K_PROT)] * g_invA[n];
    }
    __syncthreads();

    float acc[3][K_PROT];
#pragma unroll
    for (int j = 0; j < 3; j++)
#pragma unroll
        for (int k = 0; k < K_PROT; k++) acc[j][k] = 0.0f;

    float pf[2][3];
    {
        const float* t0 = tok + (size_t)rn[0]*DIM;
        pf[0][0] = t0[tid]; pf[0][1] = t0[tid+256]; pf[0][2] = t0[tid+512];
    }
    if (nr > 1) {
        const float* t1 = tok + (size_t)rn[1]*DIM;
        pf[1][0] = t1[tid]; pf[1][1] = t1[tid+256]; pf[1][2] = t1[tid+512];
    }
    for (int r = 0; r < nr; r++) {
        float a0 = pf[r&1][0], a1 = pf[r&1][1], a2 = pf[r&1][2];
        if (r + 2 < nr) {
            const float* tq = tok + (size_t)rn[r+2]*DIM;
            pf[r&1][0] = tq[tid]; pf[r&1][1] = tq[tid+256]; pf[r&1][2] = tq[tid+512];
        }
#pragma unroll
        for (int k = 0; k < K_PROT; k++) {
            float q = qs[r*K_PROT + k];
            acc[0][k] += q * a0;
            acc[1][k] += q * a1;
            acc[2][k] += q * a2;
        }
    }
    float* P = g_Pacc + (size_t)c * (K_PROT*DIM);
#pragma unroll
    for (int k = 0; k < K_PROT; k++)
#pragma unroll
        for (int j = 0; j < 3; j++)
            atomicAdd(&P[k*DIM + tid + j*256], acc[j][k]);
}

// ---------------- EMA prototype update ----------------
__global__ void combine_k(const float* __restrict__ proto, float* __restrict__ out_np) {
    int i = blockIdx.x * 256 + threadIdx.x;
    if (i >= SZ_NP) return;
    int c = i / (K_PROT*DIM);
    float p = proto[i];
    out_np[i] = (g_count[c] > 0) ? 0.999f*p + 0.001f*g_Pacc[i] : p;
}

// ---------------- launch ----------------
extern "C" void kernel_launch(void* const* d_in, const int* in_sizes, int n_in,
                              void* d_out, int out_size) {
    const float*    tok    = (const float*)d_in[0];
    const float*    proto  = (const float*)d_in[1];
    const float*    sa     = (const float*)d_in[2];
    const float*    scale  = (const float*)d_in[3];
    const int*      labels = (const int*)d_in[4];
    const unsigned* masks  = (const unsigned*)d_in[5];

    float* out      = (float*)d_out;
    float* out_pp   = out;
    float* out_img  = out_pp  + SZ_PP;
    float* out_cls  = out_img + SZ_IMG;
    float* out_part = out_cls + SZ_CLS;
    float* out_np   = out_part + SZ_PART;
    float* out_pl   = out_np  + SZ_NP;

    const int GEMM_SMEM = STAGES * STG_BYTES;   // 81920
    cudaFuncSetAttribute(gemm_mma, cudaFuncAttributeMaxDynamicSharedMemorySize, GEMM_SMEM);

    zero_k<<<(SZ_NP + 255)/256, 256>>>();
    conv_k<0><<<BN_TOT*32/256, 256>>>(tok, BN_TOT);
    conv_k<1><<<NPAD*32/256, 256>>>(proto, CK);
    {
        dim3 grid(NPAD/128, BN_TOT/128);   // (8, 128)
        gemm_mma<<<grid, 128, GEMM_SMEM>>>(out_pp);
    }
    mean2<<<(SZ_IMG + 255)/256, 256>>>(out_img);
    cls_logits<<<(SZ_CLS + 255)/256, 256>>>(out_img, sa, scale, out_cls);
    sk_init<<<BN_TOT/256, 256>>>(out_pp, labels, masks, out_pl);
    worklist_k<<<1, 256>>>();
    sk_iter<0><<<BN_TOT/256, 256>>>(labels, out_part);
    sk_iter<1><<<BN_TOT/256, 256>>>(labels, out_part);
    sk_iter<2><<<BN_TOT/256, 256>>>(labels, out_part);
    pnew_k<<<768, 256>>>(tok);
    combine_k<<<(SZ_NP + 255)/256, 256>>>(proto, out_np);
}

// round 12
// speedup vs baseline: 1.3619x; 1.0049x over previous
#include <cuda_runtime.h>
#include <cuda_bf16.h>
#include <cstdint>

// ---------------- problem constants ----------------
#define C_CLS   201
#define K_PROT  5
#define DIM     768
#define B_IMG   64
#define NP      256
#define BN_TOT  16384
#define CK      1005
#define NPAD    1024
#define KSPLIT  2304          // duplicated: A'=[Ah|Ah|Al], B'=[Bh|Bl|Bh]
#define EPSV    1e-12f

#define SZ_PP   (BN_TOT*CK)
#define SZ_IMG  (B_IMG*CK)
#define SZ_CLS  (B_IMG*(C_CLS-1))
#define SZ_PART (BN_TOT)
#define SZ_NP   (C_CLS*K_PROT*DIM)

// ---------------- device scratch ----------------
__device__ __nv_bfloat16 g_Abf[(size_t)BN_TOT*KSPLIT];   // 75.5 MB
__device__ __nv_bfloat16 g_Bbf[(size_t)NPAD*KSPLIT];     // 4.7 MB
__device__ float g_invA[BN_TOT];
__device__ int   g_pl[BN_TOT];
__device__ int   g_rowlist[C_CLS*BN_TOT];
__device__ int   g_count[C_CLS];
__device__ float g_Q[BN_TOT*K_PROT];
__device__ float g_colsum[4][C_CLS*K_PROT];
__device__ float g_Pacc[SZ_NP];
__device__ float g_part[128*1024];    // per row-block column sums
__device__ int   g_wl[1024];          // packed (class<<16)|chunk
__device__ int   g_nw;

__device__ __forceinline__ uint32_t smem_u32(const void* p) {
    uint32_t a;
    asm("{ .reg .u64 t; cvta.to.shared.u64 t, %1; cvt.u32.u64 %0, t; }" : "=r"(a) : "l"(p));
    return a;
}

// ---------------- merged setup: zero scratch + conv A + conv B ----------------
// blocks [0, NZB): zero ; [NZB, NZB+2048): conv A (8 rows/blk) ; [+128): conv B
#define NZB  ((SZ_NP + 255)/256)     // 3016
#define NCA  (BN_TOT/8)              // 2048
#define NCB  (NPAD/8)                // 128
union B4 { __nv_bfloat162 h[2]; uint2 u; };

__global__ void __launch_bounds__(256) setup_k(const float* __restrict__ tok,
                                               const float* __restrict__ proto) {
    int blk = blockIdx.x;
    int tid = threadIdx.x;
    if (blk < NZB) {
        int i = blk * 256 + tid;
        if (i < SZ_NP)  g_Pacc[i] = 0.0f;
        if (i < C_CLS)  g_count[i] = 0;
        if (i < 4*C_CLS*K_PROT) ((float*)g_colsum)[i] = 0.0f;
        return;
    }
    int mode, gw;
    const float* in;
    if (blk < NZB + NCA) { mode = 0; gw = (blk - NZB)*8 + (tid >> 5); in = tok; }
    else                 { mode = 1; gw = (blk - NZB - NCA)*8 + (tid >> 5); in = proto; }
    int lane = tid & 31;
    __nv_bfloat16* dst = (mode == 0 ? g_Abf : g_Bbf) + (size_t)gw * KSPLIT;
    if (mode == 1 && gw >= CK) {
        uint2 z = make_uint2(0u, 0u);
        uint2* d2 = (uint2*)dst;
#pragma unroll
        for (int j = 0; j < 18; j++) d2[lane + j*32] = z;
        return;
    }
    const float4* ip = (const float4*)(in + (size_t)gw * DIM);
    float4 v[6]; float s = 0.0f;
#pragma unroll
    for (int j = 0; j < 6; j++) {
        v[j] = ip[lane + j*32];
        s += v[j].x*v[j].x + v[j].y*v[j].y + v[j].z*v[j].z + v[j].w*v[j].w;
    }
#pragma unroll
    for (int o = 16; o; o >>= 1) s += __shfl_xor_sync(0xffffffffu, s, o);
    float inv = 1.0f / (sqrtf(s) + EPSV);
    if (mode == 0 && lane == 0) g_invA[gw] = inv;
#pragma unroll
    for (int j = 0; j < 6; j++) {
        int c = 4*lane + 128*j;
        float a0 = v[j].x*inv, a1 = v[j].y*inv, a2 = v[j].z*inv, a3 = v[j].w*inv;
        B4 hi, lo;
        hi.h[0] = __float22bfloat162_rn(make_float2(a0, a1));
        hi.h[1] = __float22bfloat162_rn(make_float2(a2, a3));
        lo.h[0] = __float22bfloat162_rn(make_float2(a0 - __bfloat162float(__low2bfloat16(hi.h[0])),
                                                   a1 - __bfloat162float(__high2bfloat16(hi.h[0]))));
        lo.h[1] = __float22bfloat162_rn(make_float2(a2 - __bfloat162float(__low2bfloat16(hi.h[1])),
                                                   a3 - __bfloat162float(__high2bfloat16(hi.h[1]))));
        if (mode == 0) {   // A' = [hi | hi | lo]
            *(uint2*)(dst + c)        = hi.u;
            *(uint2*)(dst + 768 + c)  = hi.u;
            *(uint2*)(dst + 1536 + c) = lo.u;
        } else {           // B' = [hi | lo | hi]
            *(uint2*)(dst + c)        = hi.u;
            *(uint2*)(dst + 768 + c)  = lo.u;
            *(uint2*)(dst + 1536 + c) = hi.u;
        }
    }
}

// ---------------- GEMM: mma.sync bf16, CTA 128x128, K=2304, linear prefetch ----------------
#define NSTAGE  72
#define STAGES  4
#define STG_BYTES 20480

__device__ __forceinline__ void ldsm4(uint32_t& r0, uint32_t& r1, uint32_t& r2, uint32_t& r3,
                                      uint32_t addr) {
    asm volatile("ldmatrix.sync.aligned.m8n8.x4.shared.b16 {%0,%1,%2,%3}, [%4];"
                 : "=r"(r0), "=r"(r1), "=r"(r2), "=r"(r3) : "r"(addr));
}
__device__ __forceinline__ void mma16816(float* c, const uint32_t* a, const uint32_t* b) {
    asm volatile("mma.sync.aligned.m16n8k16.row.col.f32.bf16.bf16.f32 "
                 "{%0,%1,%2,%3}, {%4,%5,%6,%7}, {%8,%9}, {%0,%1,%2,%3};"
                 : "+f"(c[0]), "+f"(c[1]), "+f"(c[2]), "+f"(c[3])
                 : "r"(a[0]), "r"(a[1]), "r"(a[2]), "r"(a[3]), "r"(b[0]), "r"(b[1]));
}
__device__ __forceinline__ void cpa16(uint32_t dst, const void* src) {
    asm volatile("cp.async.cg.shared.global [%0], [%1], 16;" :: "r"(dst), "l"(src));
}

__global__ void __launch_bounds__(128, 2) gemm_mma(float* __restrict__ Cout) {
    extern __shared__ char sm[];

    int tid = threadIdx.x;
    int lane = tid & 31;
    int warp = tid >> 5;
    int wm = warp & 1;
    int wn = warp >> 1;
    int row0 = blockIdx.y * 128;
    int col0 = blockIdx.x * 128;

    uint32_t sbase = smem_u32(sm);
    const char* gA = (const char*)g_Abf + (size_t)(row0 + tid) * (KSPLIT*2);
    const char* gB = (const char*)g_Bbf + (size_t)(col0 + tid) * (KSPLIT*2);

    uint32_t a_lane = (uint32_t)((((lane >> 3) & 1)*8 + (lane & 7))*80 + ((lane >> 4) & 1)*16);
    uint32_t b_lane = (uint32_t)((((lane >> 4) & 1)*8 + (lane & 7))*80 + ((lane >> 3) & 1)*16);
    uint32_t a_off = (uint32_t)(wm*64)*80 + a_lane;
    uint32_t b_off = 10240u + (uint32_t)(wn*64)*80 + b_lane;

    float acc[4][8][4];
#pragma unroll
    for (int i = 0; i < 4; i++)
#pragma unroll
        for (int j = 0; j < 8; j++)
#pragma unroll
            for (int r = 0; r < 4; r++) acc[i][j][r] = 0.0f;

#pragma unroll
    for (int p = 0; p < STAGES - 1; p++) {
        uint32_t dA = sbase + p*STG_BYTES + tid*80;
        const char* pA = gA + p*64;
        const char* pB = gB + p*64;
#pragma unroll
        for (int c = 0; c < 4; c++) {
            cpa16(dA + c*16, pA + c*16);
            cpa16(dA + 10240 + c*16, pB + c*16);
        }
        asm volatile("cp.async.commit_group;" ::: "memory");
    }

    for (int s = 0; s < NSTAGE; s++) {
        asm volatile("cp.async.wait_group 2;" ::: "memory");
        __syncthreads();
        uint32_t stg = sbase + (uint32_t)(s & 3)*STG_BYTES;
        uint32_t ab = stg + a_off;
        uint32_t bb = stg + b_off;
#pragma unroll
        for (int ks = 0; ks < 2; ks++) {
            uint32_t af[4][4], bf[4][4];
#pragma unroll
            for (int i = 0; i < 4; i++)
                ldsm4(af[i][0], af[i][1], af[i][2], af[i][3], ab + ks*32 + i*16*80);
#pragma unroll
            for (int j = 0; j < 4; j++)
                ldsm4(bf[j][0], bf[j][1], bf[j][2], bf[j][3], bb + ks*32 + j*16*80);
#pragma unroll
            for (int im = 0; im < 4; im++)
#pragma unroll
                for (int j = 0; j < 4; j++) {
                    mma16816(acc[im][2*j],   af[im], &bf[j][0]);
                    mma16816(acc[im][2*j+1], af[im], &bf[j][2]);
                }
        }
        if (s + STAGES - 1 < NSTAGE) {
            int p = s + STAGES - 1;
            uint32_t dA = sbase + (uint32_t)(p & 3)*STG_BYTES + tid*80;
            const char* pA = gA + p*64;
            const char* pB = gB + p*64;
#pragma unroll
            for (int c = 0; c < 4; c++) {
                cpa16(dA + c*16, pA + c*16);
                cpa16(dA + 10240 + c*16, pB + c*16);
            }
        }
        asm volatile("cp.async.commit_group;" ::: "memory");
    }

    // fused patch-mean partials
    float cs[16];
#pragma unroll
    for (int j = 0; j < 8; j++)
#pragma unroll
        for (int h = 0; h < 2; h++) {
            float v = 0.0f;
#pragma unroll
            for (int im = 0; im < 4; im++) v += acc[im][j][h] + acc[im][j][h+2];
            cs[j*2+h] = v;
        }
#pragma unroll
    for (int o = 4; o <= 16; o <<= 1)
#pragma unroll
        for (int t = 0; t < 16; t++) cs[t] += __shfl_xor_sync(0xffffffffu, cs[t], o);

    __syncthreads();
    float* scol = (float*)sm;
    if (lane < 4) {
#pragma unroll
        for (int j = 0; j < 8; j++) {
            scol[wm*128 + wn*64 + lane*2 + j*8]     = cs[j*2];
            scol[wm*128 + wn*64 + lane*2 + j*8 + 1] = cs[j*2+1];
        }
    }
    __syncthreads();
    if (tid < 128)
        g_part[blockIdx.y*1024 + col0 + tid] = scol[tid] + scol[128 + tid];

    // epilogue: scalar stores (CK=1005 odd -> rows not 8B aligned)
    int mb = row0 + wm*64 + (lane >> 2);
    int nb0 = col0 + wn*64 + (lane & 3)*2;
#pragma unroll
    for (int im = 0; im < 4; im++) {
        size_t r0 = (size_t)(mb + im*16) * CK;
        size_t r1 = (size_t)(mb + im*16 + 8) * CK;
#pragma unroll
        for (int j = 0; j < 8; j++) {
            int n = nb0 + j*8;
            if (n < CK) {
                Cout[r0 + n] = acc[im][j][0];
                Cout[r1 + n] = acc[im][j][2];
            }
            if (n + 1 < CK) {
                Cout[r0 + n + 1] = acc[im][j][1];
                Cout[r1 + n + 1] = acc[im][j][3];
            }
        }
    }
}

// ---------------- merged: patch-mean + class logits + Sinkhorn init ----------------
// blocks [0, 252): img mean ; [252, 302): class logits ; [302, 366): sk_init
#define NMB  ((SZ_IMG + 255)/256)    // 252
#define NCLB ((SZ_CLS + 255)/256)    // 50
#define NSKB (BN_TOT/256)            // 64

__global__ void __launch_bounds__(256) meancls_sk_k(const float* __restrict__ L,
                                                    const float* __restrict__ sa,
                                                    const float* __restrict__ scale_p,
                                                    const int* __restrict__ labels,
                                                    const unsigned* __restrict__ masks,
                                                    float* __restrict__ img,
                                                    float* __restrict__ out_cls,
                                                    float* __restrict__ out_pl) {
    int blk = blockIdx.x;
    int tid = threadIdx.x;
    if (blk < NMB) {
        int idx = blk * 256 + tid;
        if (idx >= SZ_IMG) return;
        int b = idx / CK, ck = idx % CK;
        img[idx] = (g_part[(2*b)*1024 + ck] + g_part[(2*b+1)*1024 + ck]) * (1.0f/256.0f);
        return;
    }
    if (blk < NMB + NCLB) {
        int idx = (blk - NMB) * 256 + tid;
        if (idx >= SZ_CLS) return;
        int b = idx / (C_CLS-1), c = idx % (C_CLS-1);
        float s[K_PROT], mx = -1e30f;
#pragma unroll
        for (int k = 0; k < K_PROT; k++) { s[k] = sa[c*K_PROT + k]; mx = fmaxf(mx, s[k]); }
        float den = 0.0f;
#pragma unroll
        for (int k = 0; k < K_PROT; k++) { s[k] = expf(s[k] - mx); den += s[k]; }
        float scale = scale_p[0];
        float acc = 0.0f;
#pragma unroll
        for (int k = 0; k < K_PROT; k++) {
            int ck = c*K_PROT + k;
            float iv = (g_part[(2*b)*1024 + ck] + g_part[(2*b+1)*1024 + ck]) * (1.0f/256.0f);
            acc += scale * iv * (s[k] / den * (float)K_PROT);
        }
        out_cls[idx] = acc;
        return;
    }
    // ---- sk_init ----
    int bn = (blk - NMB - NCLB) * 256 + tid;
    int lab = labels[bn >> 8];
    bool fg = (masks[bn] != 0u);
    int pl = fg ? lab : (C_CLS - 1);
    g_pl[bn] = pl;
    out_pl[bn] = (float)pl;
    int pos = atomicAdd(&g_count[pl], 1);
    g_rowlist[pl*BN_TOT + pos] = bn;

    const float* lp = L + (size_t)bn*CK + pl*K_PROT;
    float q[K_PROT], mx = lp[0];
#pragma unroll
    for (int k = 0; k < K_PROT; k++) { q[k] = lp[k]; mx = fmaxf(mx, q[k]); }
    float den = 0.0f;
#pragma unroll
    for (int k = 0; k < K_PROT; k++) { q[k] = expf(q[k] - mx); den += q[k]; }
    float sf[K_PROT], sb[K_PROT];
#pragma unroll
    for (int k = 0; k < K_PROT; k++) {
        q[k] = q[k] / den;
        g_Q[bn*K_PROT + k] = q[k];
        sf[k] = fg ? q[k] : 0.0f;
        sb[k] = fg ? 0.0f : q[k];
    }
#pragma unroll
    for (int o = 16; o; o >>= 1)
#pragma unroll
        for (int k = 0; k < K_PROT; k++) {
            sf[k] += __shfl_xor_sync(0xffffffffu, sf[k], o);
            sb[k] += __shfl_xor_sync(0xffffffffu, sb[k], o);
        }
    if ((tid & 31) == 0) {
#pragma unroll
        for (int k = 0; k < K_PROT; k++) {
            atomicAdd(&g_colsum[0][lab*K_PROT + k], sf[k]);
            atomicAdd(&g_colsum[0][(C_CLS-1)*K_PROT + k], sb[k]);
        }
    }
}

// ---------------- Sinkhorn iteration (row-parallel); IT==0 also builds worklist ----------------
#define PR 32
template <int IT>
__global__ void __launch_bounds__(256) sk_iter(const int* __restrict__ labels,
                                               float* __restrict__ out_part) {
    int blk = blockIdx.x;
    int tid = threadIdx.x;
    if (IT == 0 && blk == NSKB) {
        // worklist block (g_count final after sk_init)
        __shared__ int sc[256];
        int n = (tid < C_CLS) ? (g_count[tid] + PR - 1) / PR : 0;
        sc[tid] = n;
        __syncthreads();
        for (int off = 1; off < 256; off <<= 1) {
            int v = (tid >= off) ? sc[tid - off] : 0;
            __syncthreads();
            sc[tid] += v;
            __syncthreads();
        }
        int end = sc[tid];
        int start = end - n;
        for (int i = 0; i < n; i++) g_wl[start + i] = (tid << 16) | i;
        if (tid == 255) g_nw = sc[255];
        return;
    }
    int bn = blk * 256 + tid;
    int lab = labels[bn >> 8];
    int pl = g_pl[bn];
    bool fg = (pl == lab);

    float q[K_PROT], rs = 0.0f;
#pragma unroll
    for (int k = 0; k < K_PROT; k++) {
        float cs = g_colsum[IT][pl*K_PROT + k] + EPSV;
        q[k] = g_Q[bn*K_PROT + k] / cs;
        rs += q[k];
    }
    rs += EPSV;
#pragma unroll
    for (int k = 0; k < K_PROT; k++) {
        q[k] = q[k] / rs;
        g_Q[bn*K_PROT + k] = q[k];
    }
    if (IT < 2) {
        float sf[K_PROT], sb[K_PROT];
#pragma unroll
        for (int k = 0; k < K_PROT; k++) {
            sf[k] = fg ? q[k] : 0.0f;
            sb[k] = fg ? 0.0f : q[k];
        }
#pragma unroll
        for (int o = 16; o; o >>= 1)
#pragma unroll
            for (int k = 0; k < K_PROT; k++) {
                sf[k] += __shfl_xor_sync(0xffffffffu, sf[k], o);
                sb[k] += __shfl_xor_sync(0xffffffffu, sb[k], o);
            }
        if ((tid & 31) == 0) {
#pragma unroll
            for (int k = 0; k < K_PROT; k++) {
                atomicAdd(&g_colsum[IT+1][lab*K_PROT + k], sf[k]);
                atomicAdd(&g_colsum[IT+1][(C_CLS-1)*K_PROT + k], sb[k]);
            }
        }
    } else {
        float best = q[0]; int bi = 0;
#pragma unroll
        for (int k = 1; k < K_PROT; k++)
            if (q[k] > best) { best = q[k]; bi = k; }
        out_part[bn] = (float)bi;
    }
}

// ---------------- prototype candidates (worklist-driven, bf16 hi reads) ----------------
__global__ void __launch_bounds__(256) pnew_k() {
    if (blockIdx.x >= g_nw) return;
    int w = g_wl[blockIdx.x];
    int c = w >> 16;
    int start = (w & 0xffff) * PR;
    int M = g_count[c];
    int nr = min(PR, M - start);
    int tid = threadIdx.x;
    __shared__ int   rn[PR];
    __shared__ float qs[PR*K_PROT];

    if (tid < nr) rn[tid] = g_rowlist[c*BN_TOT + start + tid];
    __syncthreads();
    for (int i = tid; i < nr*K_PROT; i += 256) {
        int n = rn[i / K_PROT];
        qs[i] = g_Q[n*K_PROT + (i % K_PROT)];
    }
    __syncthreads();

    float acc[3][K_PROT];
#pragma unroll
    for (int j = 0; j < 3; j++)
#pragma unroll
        for (int k = 0; k < K_PROT; k++) acc[j][k] = 0.0f;

    // tok_norm = hi column of g_Abf (first 768 cols; already tok*invA)
    float pf[2][3];
    {
        const __nv_bfloat16* t0 = g_Abf + (size_t)rn[0]*KSPLIT;
        pf[0][0] = __bfloat162float(t0[tid]);
        pf[0][1] = __bfloat162float(t0[tid+256]);
        pf[0][2] = __bfloat162float(t0[tid+512]);
    }
    if (nr > 1) {
        const __nv_bfloat16* t1 = g_Abf + (size_t)rn[1]*KSPLIT;
        pf[1][0] = __bfloat162float(t1[tid]);
        pf[1][1] = __bfloat162float(t1[tid+256]);
        pf[1][2] = __bfloat162float(t1[tid+512]);
    }
    for (int r = 0; r < nr; r++) {
        float a0 = pf[r&1][0], a1 = pf[r&1][1], a2 = pf[r&1][2];
        if (r + 2 < nr) {
            const __nv_bfloat16* tq = g_Abf + (size_t)rn[r+2]*KSPLIT;
            pf[r&1][0] = __bfloat162float(tq[tid]);
            pf[r&1][1] = __bfloat162float(tq[tid+256]);
            pf[r&1][2] = __bfloat162float(tq[tid+512]);
        }
#pragma unroll
        for (int k = 0; k < K_PROT; k++) {
            float q = qs[r*K_PROT + k];
            acc[0][k] += q * a0;
            acc[1][k] += q * a1;
            acc[2][k] += q * a2;
        }
    }
    float* P = g_Pacc + (size_t)c * (K_PROT*DIM);
#pragma unroll
    for (int k = 0; k < K_PROT; k++)
#pragma unroll
        for (int j = 0; j < 3; j++)
            atomicAdd(&P[k*DIM + tid + j*256], acc[j][k]);
}

// ---------------- EMA prototype update ----------------
__global__ void combine_k(const float* __restrict__ proto, float* __restrict__ out_np) {
    int i = blockIdx.x * 256 + threadIdx.x;
    if (i >= SZ_NP) return;
    int c = i / (K_PROT*DIM);
    float p = proto[i];
    out_np[i] = (g_count[c] > 0) ? 0.999f*p + 0.001f*g_Pacc[i] : p;
}

// ---------------- launch ----------------
extern "C" void kernel_launch(void* const* d_in, const int* in_sizes, int n_in,
                              void* d_out, int out_size) {
    const float*    tok    = (const float*)d_in[0];
    const float*    proto  = (const float*)d_in[1];
    const float*    sa     = (const float*)d_in[2];
    const float*    scale  = (const float*)d_in[3];
    const int*      labels = (const int*)d_in[4];
    const unsigned* masks  = (const unsigned*)d_in[5];

    float* out      = (float*)d_out;
    float* out_pp   = out;
    float* out_img  = out_pp  + SZ_PP;
    float* out_cls  = out_img + SZ_IMG;
    float* out_part = out_cls + SZ_CLS;
    float* out_np   = out_part + SZ_PART;
    float* out_pl   = out_np  + SZ_NP;

    const int GEMM_SMEM = STAGES * STG_BYTES;   // 81920
    cudaFuncSetAttribute(gemm_mma, cudaFuncAttributeMaxDynamicSharedMemorySize, GEMM_SMEM);

    setup_k<<<NZB + NCA + NCB, 256>>>(tok, proto);
    {
        dim3 grid(NPAD/128, BN_TOT/128);   // (8, 128)
        gemm_mma<<<grid, 128, GEMM_SMEM>>>(out_pp);
    }
    meancls_sk_k<<<NMB + NCLB + NSKB, 256>>>(out_pp, sa, scale, labels, masks,
                                             out_img, out_cls, out_pl);
    sk_iter<0><<<NSKB + 1, 256>>>(labels, out_part);
    sk_iter<1><<<NSKB, 256>>>(labels, out_part);
    sk_iter<2><<<NSKB, 256>>>(labels, out_part);
    pnew_k<<<768, 256>>>();
    combine_k<<<(SZ_NP + 255)/256, 256>>>(proto, out_np);
}